// round 14
// baseline (speedup 1.0000x reference)
#include <cuda_runtime.h>

// Spatial correlation: out[b, di*9+dj, i, j] = (1/256) * sum_c x[b,c,i,j] * y[b,c,i+di-4, j+dj-4]
// x,y: [16, 256, 64, 64] f32, zero padding.
//
// Round-12: 8-pixel scalar-FFMA threads + sigma-padded conflict-free smem + single wave.
//   Thread: 8 j x 1 di x 9 dj = 72 fp32 accumulators, plain fmaf (no f32x2 packing).
//   Block: 288 thr = 8jg x 9dg x 4ti (warp = one dg, 8jg x 4ti), TI=4 rows.
//   Grid: 16 i-tiles x 16 batches = 256 blocks, 2/SM -> ALL resident (single wave).
//   Smem: 16B chunk c stored at slot c+(c>>1) => lane jg hits subbank 3jg+.. :
//   every LDS.128 phase conflict-free (3jg mod 8 is a permutation).
//   Ring: 4 stages x 2 channels, wait_group 2 (prefetch distance 3), zero-fill halo.

#define TI 4
#define SROWS 12                  // TI + 8 halo rows
#define YROWF 104                 // 26 slots * 4 floats (18 chunks sigma-padded)
#define YCHF  (SROWS * YROWF)     // 1248 floats per y channel
#define XROWF 96                  // 24 slots * 4 floats (16 chunks sigma-padded)
#define XCHF  (TI * XROWF)        // 384 floats per x channel
#define XBASEF (2 * YCHF)         // 2496
#define STAGE_F (2 * YCHF + 2 * XCHF)   // 3264 floats = 13056 B
#define STAGES 4
#define NTHREADS 288
#define NCHUNK 560                // 2*12*18 y + 2*4*16 x chunks per stage
#define NSTAGE_TOT 128            // 256 channels / 2

__device__ __forceinline__ void cp16(unsigned saddr, const float* g, int nbytes) {
    asm volatile("cp.async.ca.shared.global [%0], [%1], 16, %2;\n"
                 :: "r"(saddr), "l"(g), "r"(nbytes));
}
#define COMMIT() asm volatile("cp.async.commit_group;\n" ::: "memory")
#define WAIT2()  asm volatile("cp.async.wait_group 2;\n" ::: "memory")

extern __shared__ float sm[];

__global__ __launch_bounds__(NTHREADS, 2)
void corr_kernel(const float* __restrict__ x,
                 const float* __restrict__ y,
                 float* __restrict__ out) {
    const int tid  = threadIdx.x;
    const int lane = tid & 31;
    const int jg = lane & 7;           // 0..7 : j-group (8 pixels)
    const int ti = lane >> 3;          // 0..3 : row in tile
    const int dg = tid >> 5;           // 0..8 : di (= warp id)
    const int b   = blockIdx.y;
    const int gi0 = blockIdx.x * TI;
    const int j0  = jg * 8;

    const float* xb = x + (size_t)b * 1048576;
    const float* yb = y + (size_t)b * 1048576;
    const unsigned smbase = (unsigned)__cvta_generic_to_shared(sm);

    // ---- staging chunk descriptors: 560 chunks/stage, <=2 per thread ----
    // stage float layout: [y ch0 : 1248][y ch1 : 1248][x ch0 : 384][x ch1 : 384]
    const float* gsrc0; unsigned dst0; int nb0;
    const float* gsrc1 = xb; unsigned dst1 = 0; int nb1 = 0;
    {
        int q = tid;                     // [0,288) -> always y (y has 432 chunks)
        int ch = q / 216, m = q % 216;
        int r  = m / 18,  c = m % 18;    // smem chunk c, global col c*4-4
        int gr = gi0 - 4 + r;
        bool ok = (gr >= 0) && (gr < 64) && (c >= 1) && (c <= 16);
        nb0   = ok ? 16 : 0;
        gsrc0 = yb + ch * 4096 + (ok ? (gr * 64 + c * 4 - 4) : 0);
        dst0  = (unsigned)((ch * YCHF + r * YROWF) * 4 + (c + (c >> 1)) * 16);
    }
    if (tid < NCHUNK - NTHREADS) {       // tid < 272, chunk q = tid + 288
        int q = tid + NTHREADS;
        if (q < 432) {                   // y chunk
            int ch = q / 216, m = q % 216;
            int r  = m / 18,  c = m % 18;
            int gr = gi0 - 4 + r;
            bool ok = (gr >= 0) && (gr < 64) && (c >= 1) && (c <= 16);
            nb1   = ok ? 16 : 0;
            gsrc1 = yb + ch * 4096 + (ok ? (gr * 64 + c * 4 - 4) : 0);
            dst1  = (unsigned)((ch * YCHF + r * YROWF) * 4 + (c + (c >> 1)) * 16);
        } else {                         // x chunk, q2 in [0,128)
            int q2 = q - 432;
            int ch = q2 / 64, m = q2 % 64;
            int r  = m / 16,  c = m % 16;
            nb1   = 16;
            gsrc1 = xb + ch * 4096 + (gi0 + r) * 64 + c * 4;
            dst1  = (unsigned)((XBASEF + ch * XCHF + r * XROWF) * 4 + (c + (c >> 1)) * 16);
        }
    }

#define REFILL(S) do { \
    unsigned _bo = smbase + (unsigned)(((S) % STAGES) * (STAGE_F * 4)); \
    cp16(_bo + dst0, gsrc0 + (size_t)(S) * 8192, nb0); \
    if (tid < NCHUNK - NTHREADS) \
        cp16(_bo + dst1, gsrc1 + (size_t)(S) * 8192, nb1); \
} while (0)

    float acc[9][8];
#pragma unroll
    for (int d = 0; d < 9; d++)
#pragma unroll
        for (int p = 0; p < 8; p++) acc[d][p] = 0.0f;

    // per-thread compute offsets (floats)
    const int yoff = (ti + dg) * YROWF + 12 * jg;   // strip base (48B * jg)
    const int xoff = XBASEF + ti * XROWF + 12 * jg;

    // ---- prologue: 3 stages in flight ----
    REFILL(0); COMMIT();
    REFILL(1); COMMIT();
    REFILL(2); COMMIT();

    for (int s = 0; s < NSTAGE_TOT; s++) {
        WAIT2();
        __syncthreads();
        if (s + STAGES - 1 < NSTAGE_TOT) REFILL(s + STAGES - 1);
        COMMIT();

        const float* st = sm + (s % STAGES) * STAGE_F;
#pragma unroll
        for (int ch = 0; ch < 2; ch++) {
            const float* ys = st + ch * YCHF + yoff;
            const float* xs = st + XBASEF + ch * XCHF - XBASEF + xoff + ch * 0; // keep simple:
            // (xoff already contains XBASEF)
            xs = st + xoff + ch * XCHF;

            // y strip: chunks 2jg..2jg+3 at sigma slots 3jg+{0,1,3,4}
            float4 f0 = *(const float4*)(ys + 0);
            float4 f1 = *(const float4*)(ys + 4);
            float4 f2 = *(const float4*)(ys + 12);
            float4 f3 = *(const float4*)(ys + 16);
            float w[16] = {f0.x, f0.y, f0.z, f0.w, f1.x, f1.y, f1.z, f1.w,
                           f2.x, f2.y, f2.z, f2.w, f3.x, f3.y, f3.z, f3.w};
            float4 xa = *(const float4*)(xs + 0);
            float4 xc = *(const float4*)(xs + 4);
            float xv[8] = {xa.x, xa.y, xa.z, xa.w, xc.x, xc.y, xc.z, xc.w};

#pragma unroll
            for (int d = 0; d < 9; d++)
#pragma unroll
                for (int p = 0; p < 8; p++)
                    acc[d][p] = fmaf(xv[p], w[d + p], acc[d][p]);
        }
    }

    // ---- epilogue: scale 1/256, coalesced float4 stores ----
    const float sc = 1.0f / 256.0f;
    const int i = gi0 + ti;
    float* ob = out + ((size_t)b * 81 + dg * 9) * 4096 + i * 64 + j0;
#pragma unroll
    for (int d = 0; d < 9; d++) {
        float4 s0 = {acc[d][0] * sc, acc[d][1] * sc, acc[d][2] * sc, acc[d][3] * sc};
        float4 s1 = {acc[d][4] * sc, acc[d][5] * sc, acc[d][6] * sc, acc[d][7] * sc};
        *(float4*)(ob + (size_t)d * 4096)     = s0;
        *(float4*)(ob + (size_t)d * 4096 + 4) = s1;
    }
}

extern "C" void kernel_launch(void* const* d_in, const int* in_sizes, int n_in,
                              void* d_out, int out_size) {
    const float* x = (const float*)d_in[0];
    const float* y = (const float*)d_in[1];
    float* out = (float*)d_out;
    cudaFuncSetAttribute(corr_kernel, cudaFuncAttributeMaxDynamicSharedMemorySize,
                         STAGES * STAGE_F * 4);
    dim3 grid(16, 16);   // 16 i-tiles (TI=4) x 16 batches
    corr_kernel<<<grid, NTHREADS, STAGES * STAGE_F * 4>>>(x, y, out);
}

// round 17
// speedup vs baseline: 1.0685x; 1.0685x over previous
#include <cuda_runtime.h>

// Spatial correlation: out[b, di*9+dj, i, j] = (1/256) * sum_c x[b,c,i,j] * y[b,c,i+di-4, j+dj-4]
// x,y: [16, 256, 64, 64] f32, zero padding.
//
// Round-15: R11 kernel with 3 resident blocks/SM (latency-bound fix).
//   Thread: 4 j-pixels x 1 di x 9 dj = 36 fp32 accumulators.
//   Block: 288 threads = 16 jg x 9 dg x 2 ti, tile = 2 rows x 64 cols.
//   Grid: 512 blocks, 3 resident/SM -> 1.15 waves, 27 warps/SM.
//   Smem ring: 4 stages x 2 channels, prefetch distance 3, 16B zero-fill halo.

#define TI       2
#define SROWS    10            // TI + 8 halo rows
#define SCOLS    72            // 64 + 8 halo cols
#define YF       (SROWS * SCOLS)   // 720 floats per channel (y tile)
#define XF       (TI * 64)         // 128 floats per channel (x tile)
#define CPS      2                 // channels per stage
#define STAGE_F  (CPS * (YF + XF)) // 1696 floats per stage
#define STAGES   4
#define NTHREADS 288
#define NCHUNK   (CPS * (YF / 4 + XF / 4))  // 424 16B chunks per stage
#define NSTAGE_TOT 128             // 256 channels / CPS

__device__ __forceinline__ void cp16(unsigned saddr, const float* g, int nbytes) {
    asm volatile("cp.async.ca.shared.global [%0], [%1], 16, %2;\n"
                 :: "r"(saddr), "l"(g), "r"(nbytes));
}
#define COMMIT() asm volatile("cp.async.commit_group;\n" ::: "memory")
#define WAIT2()  asm volatile("cp.async.wait_group 2;\n" ::: "memory")

__global__ __launch_bounds__(NTHREADS, 3)
void corr_kernel(const float* __restrict__ x,
                 const float* __restrict__ y,
                 float* __restrict__ out) {
    __shared__ __align__(16) float sm[STAGES * STAGE_F];   // 27136 B

    const int tid = threadIdx.x;
    const int jg  = tid & 15;          // 0..15 : j-group (4 pixels)
    const int dg  = (tid >> 4) % 9;    // 0..8  : di
    const int ti  = tid / 144;         // 0..1  : row within tile
    const int b   = blockIdx.y;
    const int gi0 = blockIdx.x * TI;
    const int j0  = jg * 4;

    const float* xb = x + (size_t)b * 1048576;
    const float* yb = y + (size_t)b * 1048576;
    const unsigned smbase = (unsigned)__cvta_generic_to_shared(sm);

    // ---- per-thread chunk assignment: 424 chunks/stage, <=2 per thread ----
    // stage float layout: [y ch0 : 720][y ch1 : 720][x ch0 : 128][x ch1 : 128]
    const float* gsrc0; unsigned dst0; int nb0;
    const float* gsrc1 = xb; unsigned dst1 = 0; int nb1 = 0;
    {
        // chunk 0: q = tid in [0,288) -> always a y chunk (y has 360 chunks)
        int q = tid;
        int ch = q / 180, m = q % 180;
        int r  = m / 18,  c4 = m % 18;    // smem col = c4*4, global col = c4*4-4
        int gr = gi0 - 4 + r;
        bool ok = (gr >= 0) && (gr < 64) && (c4 >= 1) && (c4 <= 16);
        nb0   = ok ? 16 : 0;
        gsrc0 = yb + ch * 4096 + (ok ? (gr * 64 + c4 * 4 - 4) : 0);
        dst0  = (unsigned)((ch * YF + r * SCOLS + c4 * 4) * 4);
    }
    if (tid < NCHUNK - NTHREADS) {       // tid < 136 : second chunk q = tid + 288
        int q = tid + NTHREADS;
        if (q < 2 * (YF / 4)) {          // y chunk (q in [288,360))
            int ch = q / 180, m = q % 180;
            int r  = m / 18,  c4 = m % 18;
            int gr = gi0 - 4 + r;
            bool ok = (gr >= 0) && (gr < 64) && (c4 >= 1) && (c4 <= 16);
            nb1   = ok ? 16 : 0;
            gsrc1 = yb + ch * 4096 + (ok ? (gr * 64 + c4 * 4 - 4) : 0);
            dst1  = (unsigned)((ch * YF + r * SCOLS + c4 * 4) * 4);
        } else {                         // x chunk (q in [360,424))
            int q2 = q - 2 * (YF / 4);   // 0..63
            int ch = q2 / 32, m = q2 % 32;
            int r  = m / 16,  cc = m % 16;
            nb1   = 16;
            gsrc1 = xb + ch * 4096 + (gi0 + r) * 64 + cc * 4;
            dst1  = (unsigned)((2 * YF + ch * XF + r * 64 + cc * 4) * 4);
        }
    }

#define REFILL(S) do { \
    unsigned _bo = smbase + (unsigned)(((S) % STAGES) * (STAGE_F * 4)); \
    cp16(_bo + dst0, gsrc0 + (size_t)(S) * (CPS * 4096), nb0); \
    if (tid < NCHUNK - NTHREADS) \
        cp16(_bo + dst1, gsrc1 + (size_t)(S) * (CPS * 4096), nb1); \
} while (0)

    float acc[9][4];
#pragma unroll
    for (int d = 0; d < 9; d++)
#pragma unroll
        for (int q = 0; q < 4; q++) acc[d][q] = 0.0f;

    // ---- prologue: 3 stages in flight ----
    REFILL(0); COMMIT();
    REFILL(1); COMMIT();
    REFILL(2); COMMIT();

    // ---- main loop over 128 stages (256 channels) ----
    for (int s = 0; s < NSTAGE_TOT; s++) {
        WAIT2();                 // stage s landed
        __syncthreads();
        if (s + STAGES - 1 < NSTAGE_TOT) REFILL(s + STAGES - 1);
        COMMIT();

        const float* st = sm + (s % STAGES) * STAGE_F;
#pragma unroll
        for (int ch = 0; ch < CPS; ch++) {
            const float* ybuf = st + ch * YF;
            const float* xbuf = st + 2 * YF + ch * XF;
            float4 xv = *(const float4*)(xbuf + ti * 64 + j0);
            const float* yr = ybuf + (ti + dg) * SCOLS + j0;
            float4 w0 = *(const float4*)(yr + 0);
            float4 w1 = *(const float4*)(yr + 4);
            float4 w2 = *(const float4*)(yr + 8);
            float wv[12] = {w0.x, w0.y, w0.z, w0.w,
                            w1.x, w1.y, w1.z, w1.w,
                            w2.x, w2.y, w2.z, w2.w};
#pragma unroll
            for (int d = 0; d < 9; d++) {
                acc[d][0] += xv.x * wv[d + 0];
                acc[d][1] += xv.y * wv[d + 1];
                acc[d][2] += xv.z * wv[d + 2];
                acc[d][3] += xv.w * wv[d + 3];
            }
        }
    }

    // ---- epilogue: scale by 1/256, coalesced float4 stores ----
    const float scale = 1.0f / 256.0f;
    float* ob = out + (size_t)b * 81 * 4096;
    const int i = gi0 + ti;
#pragma unroll
    for (int d = 0; d < 9; d++) {
        const int p = dg * 9 + d;
        float4 v;
        v.x = acc[d][0] * scale;
        v.y = acc[d][1] * scale;
        v.z = acc[d][2] * scale;
        v.w = acc[d][3] * scale;
        *(float4*)(ob + (size_t)p * 4096 + i * 64 + j0) = v;
    }
}

extern "C" void kernel_launch(void* const* d_in, const int* in_sizes, int n_in,
                              void* d_out, int out_size) {
    const float* x = (const float*)d_in[0];
    const float* y = (const float*)d_in[1];
    float* out = (float*)d_out;
    dim3 grid(32, 16);   // 32 i-tiles (TI=2) x 16 batches
    corr_kernel<<<grid, NTHREADS>>>(x, y, out);
}